// round 5
// baseline (speedup 1.0000x reference)
#include <cuda_runtime.h>
#include <cuda_bf16.h>
#include <cstdint>

// Sobel conv (cross-correlation, SAME zero padding) + sign-difference maps.
// Scalar-lane rolling-register design: no shared memory, no barriers.
// Each warp owns a 32-col strip (one col per lane), RS output rows.
// Everything (x loads, y / y0 / y1 stores) is lane-stride-4B coalesced.
// Column halo via shuffles + predicated edge loads; 3-row separable window.

#define IMG_W 1024
#define IMG_H 1024
#define RS 16            // output rows per warp
#define NWARP 8          // warps per block
#define NT (NWARP * 32)

__device__ __forceinline__ float fsign(float v) {
    return (float)((v > 0.0f) - (v < 0.0f));
}

__global__ __launch_bounds__(NT, 6)
void sobel_sign_kernel(const float* __restrict__ x,
                       float* __restrict__ y,
                       float* __restrict__ y0,
                       float* __restrict__ y1) {
    const int lane = threadIdx.x & 31;
    const int wid  = threadIdx.x >> 5;
    const int b    = blockIdx.z;
    const int w0   = blockIdx.x * 32;                   // strip base col
    const int r0   = (blockIdx.y * NWARP + wid) * RS;   // first output row
    const int w    = w0 + lane;                         // this lane's col

    const float* __restrict__ xb = x + (size_t)b * IMG_H * IMG_W;
    float* __restrict__ ybx = y + (size_t)b * 2 * IMG_H * IMG_W;
    float* __restrict__ yby = ybx + (size_t)IMG_H * IMG_W;
    const size_t obase = (size_t)b * (size_t)(IMG_H - 1) * (IMG_W - 1);

    const bool lane0  = (lane == 0);
    const bool lane31 = (lane == 31);
    const bool has_l  = (w0 > 0);
    const bool has_r  = (w0 + 32 < IMG_W);
    const bool emit_c = (w < IMG_W - 1);   // y0/y1 defined for cols 0..1022

    // rolling 3-row window: hd = x[c-1]-x[c+1], hs = x[c-1]+2x[c]+x[c+1]
    // hdR: same as hd but for col w0+32 (only lane31's value is used)
    float hdP1 = 0.f, hdP2 = 0.f, hsP1 = 0.f, hsP2 = 0.f;
    float hdRP1 = 0.f, hdRP2 = 0.f;
    float sgyP = 0.f;

    #pragma unroll
    for (int i = 0; i < RS + 3; i++) {
        const int j = r0 - 1 + i;                 // input row for this step

        float v = 0.f, lf = 0.f, rt = 0.f, rt2 = 0.f;
        if ((unsigned)j < (unsigned)IMG_H) {
            const float* row = xb + (size_t)j * IMG_W;
            v = __ldg(row + w);
            if (lane0 && has_l) lf = __ldg(row + (w0 - 1));
            if (lane31 && has_r) {
                const float2 t2 = *reinterpret_cast<const float2*>(row + (w0 + 32));
                rt = t2.x; rt2 = t2.y;
            }
        }
        float left  = __shfl_up_sync(0xffffffffu, v, 1);
        float right = __shfl_down_sync(0xffffffffu, v, 1);
        if (lane0)  left  = lf;
        if (lane31) right = rt;

        const float hd  = left - right;
        const float hs  = fmaf(2.f, v, left + right);
        const float hdR = v - rt2;                // col w0+32 (lane31 only)

        if (i >= 2) {
            const int m = r0 + i - 2;             // row with complete vertical window
            const float gy  = hsP2 - hs;
            const float sgy = fsign(gy);

            if (i <= RS + 1) {                    // emit y + y0 for rows r0..r0+RS-1
                const float gx  = fmaf(2.f, hdP1, hdP2 + hd);
                const float gxR = fmaf(2.f, hdRP1, hdRP2 + hdR);

                ybx[(size_t)m * IMG_W + w] = gx;
                yby[(size_t)m * IMG_W + w] = gy;

                const float sgx = fsign(gx);
                float sxn = __shfl_down_sync(0xffffffffu, sgx, 1);
                if (lane31) sxn = fsign(gxR);

                if (m < IMG_H - 1 && emit_c)
                    y0[obase + (size_t)m * (IMG_W - 1) + w] = sgx - sxn;
            }
            if (i >= 3) {
                const int m1 = m - 1;             // y1 row m1 needs sgy[m1], sgy[m1+1]
                if (m1 < IMG_H - 1 && emit_c)
                    y1[obase + (size_t)m1 * (IMG_W - 1) + w] = sgyP - sgy;
            }
            sgyP = sgy;
        }
        hdP2 = hdP1;  hdP1 = hd;
        hsP2 = hsP1;  hsP1 = hs;
        hdRP2 = hdRP1; hdRP1 = hdR;
    }
}

extern "C" void kernel_launch(void* const* d_in, const int* in_sizes, int n_in,
                              void* d_out, int out_size) {
    const float* x = (const float*)d_in[0];
    const int B = in_sizes[0] / (IMG_H * IMG_W);

    float* y  = (float*)d_out;
    float* y0 = y  + (size_t)B * 2 * IMG_H * IMG_W;
    float* y1 = y0 + (size_t)B * (IMG_H - 1) * (IMG_W - 1);

    dim3 block(NT, 1, 1);
    dim3 grid(IMG_W / 32, IMG_H / (RS * NWARP), B);
    sobel_sign_kernel<<<grid, block>>>(x, y, y0, y1);
}